// round 5
// baseline (speedup 1.0000x reference)
#include <cuda_runtime.h>
#include <cuda_bf16.h>
#include <cstdint>

// N = 1048576 rows, D = 64 f32 per row (256 B/row).
constexpr int N_ELEMS = 1 << 20;
constexpr int TILE    = 256;                 // rows per block
constexpr int NTILES  = N_ELEMS / TILE;      // 4096

// Decoupled look-back state. Packed word: [23:64) epoch, [21:23) flag, [0:21) value.
// flag: 0 = invalid/stale, 1 = aggregate ready, 2 = inclusive prefix ready.
// Epoch comes from the monotonically increasing ticket counter, so stale words
// from earlier launches/replays are automatically invalid — no reset needed.
__device__ unsigned long long g_ticket;            // zero-init at load, grows forever
__device__ unsigned long long g_state[NTILES];

__global__ void __launch_bounds__(256) stitch_k(
        const int*    __restrict__ part,
        const int*    __restrict__ idx0,
        const int*    __restrict__ idx1,
        const float4* __restrict__ in,
        float4*       __restrict__ out) {
    __shared__ unsigned long long s_ticket;
    __shared__ int wsum[8];
    __shared__ int s_run;
    __shared__ int sdest[TILE];

    int t = threadIdx.x;
    if (t == 0) s_ticket = atomicAdd(&g_ticket, 1ULL);
    __syncthreads();
    unsigned long long ticket = s_ticket;
    int tile = (int)(ticket & (unsigned long long)(NTILES - 1));
    unsigned long long epoch = ticket >> 12;     // exactly 4096 tickets per launch

    int gi = tile * TILE + t;
    const float4* src = in + (size_t)tile * (TILE * 16);

    // --- prefetch first half of the tile's row data (32 regs, long-latency) ---
    float4 v[8];
    #pragma unroll
    for (int k = 0; k < 8; k++) v[k] = src[t + k * 256];

    // --- partition predicate + warp ballot ---
    int b = (part[gi] == 0);
    int lane = t & 31, w = t >> 5;
    unsigned bal = __ballot_sync(0xffffffffu, b);
    int within = __popc(bal & ((1u << lane) - 1u));
    if (lane == 0) wsum[w] = __popc(bal);
    __syncthreads();

    // --- warp 0: publish aggregate, look back, publish prefix ---
    if (w == 0) {
        int cnt = 0;
        #pragma unroll
        for (int i = 0; i < 8; i++) cnt += wsum[i];

        if (lane == 0)
            atomicExch(&g_state[tile],
                       (epoch << 23) | (1ULL << 21) | (unsigned long long)cnt);

        int running = 0;
        int base = tile;
        while (base > 0) {
            int i = base - 1 - lane;          // lane 0 = nearest predecessor
            int val = 0, fl = 0;
            if (i >= 0) {
                unsigned long long s = *(volatile unsigned long long*)&g_state[i];
                if ((s >> 23) == epoch) {
                    fl  = (int)((s >> 21) & 3ULL);
                    val = (int)(s & 0x1FFFFFULL);
                }
            }
            unsigned ready = __ballot_sync(0xffffffffu, i < 0 || fl != 0);
            if (ready != 0xffffffffu) continue;           // spin until window A-ready
            unsigned hasP = __ballot_sync(0xffffffffu, i >= 0 && fl == 2);
            if (hasP) {
                int firstP = __ffs(hasP) - 1;             // nearest prefix
                int contrib = (lane <= firstP) ? val : 0; // aggs below + prefix at firstP
                running += __reduce_add_sync(0xffffffffu, contrib);
                break;
            } else {
                running += __reduce_add_sync(0xffffffffu, val);
                base -= 32;
            }
        }
        if (lane == 0) {
            atomicExch(&g_state[tile],
                       (epoch << 23) | (2ULL << 21) |
                       (unsigned long long)(cnt + running));
            s_run = running;                   // zeros before this tile
        }
    }
    __syncthreads();

    // --- per-element destination ---
    int woff = 0;
    #pragma unroll
    for (int i = 0; i < 8; i++) woff += (i < w) ? wsum[i] : 0;
    int zb = s_run + woff + within;            // global zeros strictly before gi
    sdest[t] = b ? __ldg(idx0 + zb) : __ldg(idx1 + (gi - zb));
    __syncthreads();

    // --- store prefetched half ---
    #pragma unroll
    for (int k = 0; k < 8; k++) {
        int s   = t + k * 256;
        int row = s >> 4;
        int ln  = s & 15;
        out[(size_t)sdest[row] * 16 + ln] = v[k];
    }
    // --- stream second half ---
    #pragma unroll
    for (int k = 8; k < 16; k++) {
        int s   = t + k * 256;
        int row = s >> 4;
        int ln  = s & 15;
        out[(size_t)sdest[row] * 16 + ln] = src[s];
    }
}

// ---------------------------------------------------------------------------
extern "C" void kernel_launch(void* const* d_in, const int* in_sizes, int n_in,
                              void* d_out, int out_size) {
    const float* data = (const float*)d_in[0];
    const int*   part = (const int*)d_in[1];
    const int*   idx0 = (const int*)d_in[2];
    const int*   idx1 = (const int*)d_in[3];
    float* out = (float*)d_out;

    stitch_k<<<NTILES, 256>>>(part, idx0, idx1,
                              (const float4*)data, (float4*)out);
}

// round 6
// speedup vs baseline: 1.0080x; 1.0080x over previous
#include <cuda_runtime.h>
#include <cuda_bf16.h>
#include <cstdint>

// N = 1048576 rows, D = 64 f32 per row (256 B/row).
constexpr int N_ELEMS = 1 << 20;
constexpr int TILE    = 256;                 // rows per block
constexpr int NTILES  = N_ELEMS / TILE;      // 4096

// Decoupled look-back state, 32-bit packed: [22:32) epoch, [20:22) flag, [0:20) value.
// flag: 0 = stale, 1 = aggregate ready, 2 = inclusive prefix ready.
// value: aggregate <= 256 or inclusive prefix <= 524288+256 (fits 20 bits).
// Epoch (10 bits) derives from the ever-growing ticket; every tile word is
// rewritten every launch, so only epoch-1 words can be stale -> no reset needed.
__device__ unsigned long long g_ticket;      // zero-init at module load
__device__ unsigned int      g_state[NTILES];

__global__ void __launch_bounds__(256) stitch_k(
        const int*    __restrict__ part,
        const int*    __restrict__ idx0,
        const int*    __restrict__ idx1,
        const float4* __restrict__ in,
        float4*       __restrict__ out) {
    __shared__ unsigned long long s_ticket;
    __shared__ int wsum[8];
    __shared__ int s_run;
    __shared__ int sdest[TILE];

    int t = threadIdx.x;
    if (t == 0) s_ticket = atomicAdd(&g_ticket, 1ULL);
    __syncthreads();
    unsigned long long ticket = s_ticket;
    int tile = (int)(ticket & (unsigned long long)(NTILES - 1));
    unsigned int epoch = (unsigned int)(ticket >> 12) & 0x3FFu;
    unsigned int etag  = epoch << 22;

    int gi = tile * TILE + t;
    const float4* src = in + (size_t)tile * (TILE * 16);

    // --- issue the part load FIRST so the tile aggregate publishes early ---
    int pv = part[gi];

    // --- prefetch first half of the tile's row data (32 regs, long latency) ---
    float4 v[8];
    #pragma unroll
    for (int k = 0; k < 8; k++) v[k] = src[t + k * 256];

    // --- partition predicate + warp ballot ---
    int b = (pv == 0);
    int lane = t & 31, w = t >> 5;
    unsigned bal = __ballot_sync(0xffffffffu, b);
    int within = __popc(bal & ((1u << lane) - 1u));
    if (lane == 0) wsum[w] = __popc(bal);
    __syncthreads();

    // --- warp 0: publish aggregate, look back, publish inclusive prefix ---
    if (w == 0) {
        int cnt = 0;
        #pragma unroll
        for (int i = 0; i < 8; i++) cnt += wsum[i];

        if (lane == 0)
            atomicExch(&g_state[tile], etag | (1u << 20) | (unsigned int)cnt);

        int running = 0;
        int base = tile;
        while (base > 0) {
            int i = base - 1 - lane;              // lane 0 = nearest predecessor
            int val = 0, fl = 0;
            if (i >= 0) {
                unsigned int s = *(volatile unsigned int*)&g_state[i];
                if ((s >> 22) == epoch) {
                    fl  = (int)((s >> 20) & 3u);
                    val = (int)(s & 0xFFFFFu);
                }
            }
            unsigned ready = __ballot_sync(0xffffffffu, i < 0 || fl != 0);
            if (ready != 0xffffffffu) continue;   // spin until window all-ready
            unsigned hasP = __ballot_sync(0xffffffffu, i >= 0 && fl == 2);
            if (hasP) {
                int firstP = __ffs(hasP) - 1;     // nearest inclusive prefix
                int contrib = (lane <= firstP) ? val : 0;
                running += __reduce_add_sync(0xffffffffu, contrib);
                break;
            } else {
                running += __reduce_add_sync(0xffffffffu, val);
                base -= 32;
            }
        }
        if (lane == 0) {
            atomicExch(&g_state[tile],
                       etag | (2u << 20) | (unsigned int)(cnt + running));
            s_run = running;                      // zeros strictly before this tile
        }
    }
    __syncthreads();

    // --- per-element destination ---
    int woff = 0;
    #pragma unroll
    for (int i = 0; i < 8; i++) woff += (i < w) ? wsum[i] : 0;
    int zb = s_run + woff + within;               // global zeros strictly before gi
    sdest[t] = b ? __ldg(idx0 + zb) : __ldg(idx1 + (gi - zb));
    __syncthreads();

    // --- store prefetched half ---
    #pragma unroll
    for (int k = 0; k < 8; k++) {
        int s   = t + k * 256;
        int row = s >> 4;
        int ln  = s & 15;
        out[(size_t)sdest[row] * 16 + ln] = v[k];
    }
    // --- stream second half ---
    #pragma unroll
    for (int k = 8; k < 16; k++) {
        int s   = t + k * 256;
        int row = s >> 4;
        int ln  = s & 15;
        out[(size_t)sdest[row] * 16 + ln] = src[s];
    }
}

// ---------------------------------------------------------------------------
extern "C" void kernel_launch(void* const* d_in, const int* in_sizes, int n_in,
                              void* d_out, int out_size) {
    const float* data = (const float*)d_in[0];
    const int*   part = (const int*)d_in[1];
    const int*   idx0 = (const int*)d_in[2];
    const int*   idx1 = (const int*)d_in[3];
    float* out = (float*)d_out;

    stitch_k<<<NTILES, 256>>>(part, idx0, idx1,
                              (const float4*)data, (float4*)out);
}